// round 13
// baseline (speedup 1.0000x reference)
#include <cuda_runtime.h>
#include <cuda_bf16.h>
#include <cstdint>

// ---------------------------------------------------------------------------
// BitLinear: y = (quant(x) @ unpack(w)^T) * (amax/(127*ws)) + bias
// x: [4,4096,2048] f32  -> M = 16384, K = 2048, N = 2048, out f32
// Plain sm_103 target. R13 = R10's per-warp hybrid mapping (every warp:
// 16-acc IMMA sub-tile on N[0,32) + 48-acc dp4a sub-tile on N[32,128);
// lowest measured busy total, 542us, no spills) combined with R11/R12's
// mbarrier pipeline (full/cons per stage, 1-chunk skew, no __syncthreads in
// the mainloop). Tensor kk-step reuses one a-frag buffer (register relief).
// ---------------------------------------------------------------------------

#define M_TOT 16384
#define N_TOT 2048
#define K_TOT 2048

#define TILE_M 128
#define TILE_N 128
#define TILE_KB 128                 // int8 K elements per pipeline stage
#define NCHUNK (K_TOT / TILE_KB)    // 16
#define NSTAGE 3
#define ROW_STRIDE 144              // 128B data + 16B pad: conflict-free
#define A_STAGE_BYTES (128 * ROW_STRIDE)      // 18432
#define STAGE_BYTES (2 * A_STAGE_BYTES)       // 36864
#define SMEM_BYTES (1024 + NSTAGE * STAGE_BYTES)  // 111616 -> 2 CTAs/SM

// -------------------------- scratch (device globals) -----------------------
__device__ __align__(128) int8_t g_xq[(size_t)M_TOT * K_TOT];  // 32 MiB
__device__ __align__(128) int8_t g_w[(size_t)N_TOT * K_TOT];   // 4 MiB
__device__ float g_rowscale[M_TOT];
__device__ int g_probe_sink;

// ------------------------------ PTX helpers --------------------------------
__device__ __forceinline__ uint32_t smem_u32(const void* p) {
    uint32_t a;
    asm("{ .reg .u64 t; cvta.to.shared.u64 t, %1; cvt.u32.u64 %0, t; }"
        : "=r"(a) : "l"(p));
    return a;
}

__device__ __forceinline__ void cpa16(uint32_t saddr, const void* gaddr) {
    asm volatile("cp.async.cg.shared.global [%0], [%1], 16;"
                 :: "r"(saddr), "l"(gaddr) : "memory");
}

#define MBARRIER_INIT(addr, cnt) \
    asm volatile("mbarrier.init.shared.b64 [%0], %1;" \
                 :: "r"((uint32_t)(addr)), "r"((uint32_t)(cnt)) : "memory")

#define MBARRIER_ARRIVE(addr) \
    asm volatile("mbarrier.arrive.shared.b64 _, [%0];" \
                 :: "r"((uint32_t)(addr)) : "memory")

#define CPASYNC_MBAR_ARRIVE(addr) \
    asm volatile("cp.async.mbarrier.arrive.noinc.shared.b64 [%0];" \
                 :: "r"((uint32_t)(addr)) : "memory")

#define MBARRIER_WAIT_PARITY(addr, ph) do {                                   \
    uint32_t _m = (uint32_t)(addr);                                           \
    uint32_t _p = (uint32_t)(ph);                                             \
    uint32_t _done;                                                           \
    asm volatile(                                                             \
        "{\n\t.reg .pred p;\n\t"                                              \
        "mbarrier.try_wait.parity.shared.b64 p, [%1], %2;\n\t"                \
        "selp.b32 %0, 1, 0, p;\n\t}"                                          \
        : "=r"(_done) : "r"(_m), "r"(_p) : "memory");                         \
    while (!_done) {                                                          \
        asm volatile(                                                         \
            "{\n\t.reg .pred p;\n\t"                                          \
            "mbarrier.try_wait.parity.shared.b64 p, [%1], %2, 0x989680;\n\t"  \
            "selp.b32 %0, 1, 0, p;\n\t}"                                      \
            : "=r"(_done) : "r"(_m), "r"(_p) : "memory");                     \
    }                                                                         \
} while (0)

__device__ __forceinline__ void ldsm4(uint32_t* r, uint32_t addr) {
    asm volatile("ldmatrix.sync.aligned.m8n8.x4.shared.b16 {%0,%1,%2,%3}, [%4];"
                 : "=r"(r[0]), "=r"(r[1]), "=r"(r[2]), "=r"(r[3]) : "r"(addr));
}

__device__ __forceinline__ void ldsm2(uint32_t* r, uint32_t addr) {
    asm volatile("ldmatrix.sync.aligned.m8n8.x2.shared.b16 {%0,%1}, [%2];"
                 : "=r"(r[0]), "=r"(r[1]) : "r"(addr));
}

__device__ __forceinline__ void imma16832(int* c, const uint32_t* a,
                                          uint32_t b0, uint32_t b1) {
    asm volatile(
        "mma.sync.aligned.m16n8k32.row.col.s32.s8.s8.s32 "
        "{%0,%1,%2,%3}, {%4,%5,%6,%7}, {%8,%9}, {%0,%1,%2,%3};"
        : "+r"(c[0]), "+r"(c[1]), "+r"(c[2]), "+r"(c[3])
        : "r"(a[0]), "r"(a[1]), "r"(a[2]), "r"(a[3]), "r"(b0), "r"(b1));
}

__device__ __forceinline__ int dp4a(int a, int b, int c) {
    int d;
    asm("dp4a.s32.s32 %0, %1, %2, %3;" : "=r"(d) : "r"(a), "r"(b), "r"(c));
    return d;
}

// --------------------------- kernel 1: quantize ----------------------------
__device__ __forceinline__ int q1(float v, float sc) {
    float q = rintf(v * sc);                 // round half to even (matches jnp)
    q = fminf(fmaxf(q, -128.0f), 127.0f);
    return (int)q;
}

__device__ __forceinline__ int pack4(float4 v, float sc) {
    int q0 = q1(v.x, sc), q2 = q1(v.z, sc);
    int q1v = q1(v.y, sc), q3 = q1(v.w, sc);
    return (q0 & 255) | ((q1v & 255) << 8) | ((q2 & 255) << 16) | (q3 << 24);
}

__global__ __launch_bounds__(256) void quant_kernel(const float* __restrict__ x,
                                                    const float* __restrict__ wsp) {
    int r = blockIdx.x;
    int t = threadIdx.x;
    const float4* xr = reinterpret_cast<const float4*>(x + (size_t)r * K_TOT);
    float4 a = xr[t];
    float4 b = xr[t + 256];
    float am = fmaxf(fmaxf(fabsf(a.x), fabsf(a.y)), fmaxf(fabsf(a.z), fabsf(a.w)));
    am = fmaxf(am, fmaxf(fmaxf(fabsf(b.x), fabsf(b.y)), fmaxf(fabsf(b.z), fabsf(b.w))));
#pragma unroll
    for (int o = 16; o; o >>= 1) am = fmaxf(am, __shfl_xor_sync(0xffffffffu, am, o));
    __shared__ float red[8];
    __shared__ float s_amax;
    if ((t & 31) == 0) red[t >> 5] = am;
    __syncthreads();
    if (t == 0) {
        float m = red[0];
#pragma unroll
        for (int i = 1; i < 8; i++) m = fmaxf(m, red[i]);
        m = fmaxf(m, 1e-5f);
        s_amax = m;
        g_rowscale[r] = __fdiv_rn(m, 127.0f * wsp[0]);
    }
    __syncthreads();
    float sc = __fdiv_rn(127.0f, s_amax);
    int* dst = reinterpret_cast<int*>(g_xq + (size_t)r * K_TOT);
    dst[t]       = pack4(a, sc);
    dst[t + 256] = pack4(b, sc);
}

// ------------------------- kernel 2: unpack weights ------------------------
__global__ __launch_bounds__(256) void unpack_kernel(const int* __restrict__ wp) {
    int idx = blockIdx.x * 256 + threadIdx.x;      // 512*2048 entries
    int p = wp[idx];
    int d = idx & (K_TOT - 1);
    int rr = idx >> 11;
#pragma unroll
    for (int i = 0; i < 4; i++) {
        int w = ((p >> (2 * i)) & 3) - 1;
        g_w[((size_t)(i * 512 + rr) << 11) + d] = (int8_t)w;
    }
}

// ------------------------- probe (launch-slot filler) ----------------------
__global__ void probe_kernel() {
    if (threadIdx.x == 0) g_probe_sink = 1;
}

// ----------------------------- kernel 3: GEMM ------------------------------
// CTA 128x128, 256 threads, 2 CTAs/SM. All 8 warps identical hybrids:
//   tensor sub-tile: M[(wid&1)*64,+64) x N[(wid>>1)*8,+8)    (acc 16 regs)
//   dp4a  sub-tile: M[(wid&3)*32,+32) x N[32+(wid>>2)*48,+48) (acc 48 regs)
// All threads load (8 cpa16/thread/chunk). Pipeline: 3 stages, mbarriers
// full[s] (256 cp.async arrivals) / cons[s] (256 consumer arrivals);
// no __syncthreads in the mainloop (1-chunk skew tolerance).
__global__ __launch_bounds__(256, 2)
void gemm_kernel(const float* __restrict__ bias, float* __restrict__ out) {
    extern __shared__ char smem[];
    const uint32_t sb = smem_u32(smem);
    const uint32_t data_base = sb + 1024;
    const int tid = threadIdx.x;
    const int lane = tid & 31;
    const int wid = tid >> 5;
    const int m_base = blockIdx.y * TILE_M;
    const int n_base = blockIdx.x * TILE_N;

#define BAR_FULL(s) (sb + (uint32_t)(s) * 8)
#define BAR_CONS(s) (sb + 24 + (uint32_t)(s) * 8)
#define STAGE_AT(s) (data_base + (uint32_t)(s) * STAGE_BYTES)

    if (tid == 0) {
#pragma unroll
        for (int s = 0; s < NSTAGE; s++) {
            MBARRIER_INIT(BAR_FULL(s), 256);
            MBARRIER_INIT(BAR_CONS(s), 256);
        }
    }
    __syncthreads();   // one-time: mbarriers visible before use

    // ---- loader coordinates (all 256 threads): 8 cpa16 per chunk ----
    const int l_lr = tid >> 3;                       // 0..31
    const int l_lc = (tid & 7) * 16;                 // byte col in 128B row
    const int8_t* l_ag = g_xq + (size_t)(m_base + l_lr) * K_TOT + l_lc;
    const int8_t* l_bg = g_w  + (size_t)(n_base + l_lr) * K_TOT + l_lc;
    const uint32_t l_sw = (uint32_t)(l_lr * ROW_STRIDE + l_lc);

    // ---------------- tensor sub-tile state ----------------
    const int wm2 = wid & 1;             // 64-row slab
    const int wn2 = wid >> 1;            // 0..3 -> 8-col slab in N[0,32)
    const uint32_t a_rel = (uint32_t)((wm2 * 64 + (lane & 15)) * ROW_STRIDE
                                      + (lane >> 4) * 16);
    const uint32_t b_rel = (uint32_t)(A_STAGE_BYTES
                 + (wn2 * 8 + (lane & 7)) * ROW_STRIDE
                 + ((lane >> 3) & 1) * 16);
    int acc[4][4];

    // ---------------- dp4a sub-tile state ------------------
    const int mslab = wid & 3;           // 32-row slab
    const int nh = wid >> 2;             // 0..1 -> 48-col half of N[32,128)
    const int lane_m = lane >> 3;        // 0..3
    const int lane_n = lane & 7;         // 0..7
    const uint32_t da_rel = (uint32_t)((mslab * 32 + lane_m) * ROW_STRIDE);
    const uint32_t db_rel = (uint32_t)(A_STAGE_BYTES
                 + (32 + nh * 48 + lane_n) * ROW_STRIDE);
    int dacc[8][6];

#pragma unroll
    for (int i = 0; i < 4; i++)
#pragma unroll
        for (int k = 0; k < 4; k++) acc[i][k] = 0;
#pragma unroll
    for (int i = 0; i < 8; i++)
#pragma unroll
        for (int j = 0; j < 6; j++) dacc[i][j] = 0;

    // ---- prologue: all threads fill stages 0 and 1 (chunks 0 and 1) ----
#pragma unroll
    for (int s = 0; s < 2; s++) {
        uint32_t st = STAGE_AT(s);
        int koff = s * TILE_KB;
#pragma unroll
        for (int i = 0; i < 4; i++) {
            cpa16(st + l_sw + i * 32 * ROW_STRIDE,
                  l_ag + koff + (size_t)i * 32 * K_TOT);
            cpa16(st + A_STAGE_BYTES + l_sw + i * 32 * ROW_STRIDE,
                  l_bg + koff + (size_t)i * 32 * K_TOT);
        }
        CPASYNC_MBAR_ARRIVE(BAR_FULL(s));
    }

    // ---- mainloop ----
    for (int kc = 0; kc < NCHUNK; kc++) {
        const int s = kc % NSTAGE;
        const int u = kc / NSTAGE;

        {
            const int kl = kc + 2;                 // chunk to load ahead
            if (kl < NCHUNK) {
                const int sl = kl % NSTAGE;
                const int ul = kl / NSTAGE;
                if (ul >= 1)                       // stage reuse: wait consumed
                    MBARRIER_WAIT_PARITY(BAR_CONS(sl), (ul - 1) & 1);
                uint32_t st = STAGE_AT(sl);
                int koff = kl * TILE_KB;
#pragma unroll
                for (int i = 0; i < 4; i++) {
                    cpa16(st + l_sw + i * 32 * ROW_STRIDE,
                          l_ag + koff + (size_t)i * 32 * K_TOT);
                    cpa16(st + A_STAGE_BYTES + l_sw + i * 32 * ROW_STRIDE,
                          l_bg + koff + (size_t)i * 32 * K_TOT);
                }
                CPASYNC_MBAR_ARRIVE(BAR_FULL(sl));
            }
        }

        MBARRIER_WAIT_PARITY(BAR_FULL(s), u & 1);
        const uint32_t st = STAGE_AT(s);

#pragma unroll
        for (int g = 0; g < 16; g++) {
            // tensor kk-step before every 4th dp4a group; single a-frag
            // buffer reused per mt (register relief vs R10's afr[4][4]).
            if ((g & 3) == 0) {
                const int kk = g >> 2;
                uint32_t bfr[2];
                ldsm2(bfr, st + b_rel + (uint32_t)(kk * 32));
#pragma unroll
                for (int mt = 0; mt < 4; mt++) {
                    uint32_t afr[4];
                    ldsm4(afr,
                          st + a_rel + (uint32_t)(mt * 16 * ROW_STRIDE + kk * 32));
                    imma16832(acc[mt], afr, bfr[0], bfr[1]);
                }
            }
            // dp4a group: batched loads (MLP 14), then 96 dp4a
            const uint32_t kb = (uint32_t)(g * 8);
            int2 av[8], bv[6];
#pragma unroll
            for (int mt = 0; mt < 8; mt++) {
                uint32_t ad = st + da_rel + (uint32_t)(mt * 4 * ROW_STRIDE) + kb;
                asm volatile("ld.shared.v2.b32 {%0,%1}, [%2];"
                             : "=r"(av[mt].x), "=r"(av[mt].y) : "r"(ad));
            }
#pragma unroll
            for (int nt = 0; nt < 6; nt++) {
                uint32_t bd = st + db_rel + (uint32_t)(nt * 8 * ROW_STRIDE) + kb;
                asm volatile("ld.shared.v2.b32 {%0,%1}, [%2];"
                             : "=r"(bv[nt].x), "=r"(bv[nt].y) : "r"(bd));
            }
#pragma unroll
            for (int mt = 0; mt < 8; mt++) {
#pragma unroll
                for (int nt = 0; nt < 6; nt++) {
                    int c = dp4a(av[mt].x, bv[nt].x, dacc[mt][nt]);
                    dacc[mt][nt] = dp4a(av[mt].y, bv[nt].y, c);
                }
            }
        }
        MBARRIER_ARRIVE(BAR_CONS(s));
    }

    // ------------------------------ epilogue -------------------------------
    // tensor part: 64M x 8N per warp
    {
        int n = n_base + wn2 * 8 + 2 * (lane & 3);
        float2 bv2 = *reinterpret_cast<const float2*>(bias + n);
#pragma unroll
        for (int mt = 0; mt < 4; mt++) {
            int m = m_base + wm2 * 64 + mt * 16 + (lane >> 2);
            float rs0 = g_rowscale[m];
            float rs1 = g_rowscale[m + 8];
            float2 v0, v1;
            v0.x = __int2float_rn(acc[mt][0]) * rs0 + bv2.x;
            v0.y = __int2float_rn(acc[mt][1]) * rs0 + bv2.y;
            v1.x = __int2float_rn(acc[mt][2]) * rs1 + bv2.x;
            v1.y = __int2float_rn(acc[mt][3]) * rs1 + bv2.y;
            *reinterpret_cast<float2*>(out + (size_t)m * N_TOT + n) = v0;
            *reinterpret_cast<float2*>(out + (size_t)(m + 8) * N_TOT + n) = v1;
        }
    }
    // dp4a part: 32M x 48N per warp
    {
        float rs[8];
#pragma unroll
        for (int mt = 0; mt < 8; mt++)
            rs[mt] = g_rowscale[m_base + mslab * 32 + mt * 4 + lane_m];
#pragma unroll
        for (int nt = 0; nt < 6; nt++) {
            int n = n_base + 32 + nh * 48 + nt * 8 + lane_n;
            float bvv = bias[n];
#pragma unroll
            for (int mt = 0; mt < 8; mt++) {
                int m = m_base + mslab * 32 + mt * 4 + lane_m;
                out[(size_t)m * N_TOT + n] =
                    __int2float_rn(dacc[mt][nt]) * rs[mt] + bvv;
            }
        }
    }
}

// ------------------------------- launcher ----------------------------------
extern "C" void kernel_launch(void* const* d_in, const int* in_sizes, int n_in,
                              void* d_out, int out_size) {
    const float* x    = (const float*)d_in[0];
    const int*   wp   = (const int*)d_in[1];
    const float* ws   = (const float*)d_in[2];
    const float* bias = (const float*)d_in[3];
    float*       out  = (float*)d_out;

    (void)in_sizes; (void)n_in; (void)out_size;

    static bool attr_set = false;
    if (!attr_set) {
        cudaFuncSetAttribute(gemm_kernel, cudaFuncAttributeMaxDynamicSharedMemorySize,
                             SMEM_BYTES);
        attr_set = true;
    }

    // Launch order keeps gemm at absolute launch #6 for ncu (-s 5 -c 1).
    unpack_kernel<<<(512 * K_TOT) / 256, 256>>>(wp);
    quant_kernel<<<M_TOT, 256>>>(x, ws);
    probe_kernel<<<1, 32>>>();
    dim3 grid(N_TOT / TILE_N, M_TOT / TILE_M);
    gemm_kernel<<<grid, 256, SMEM_BYTES>>>(bias, out);
}

// round 14
// speedup vs baseline: 1.2890x; 1.2890x over previous
#include <cuda_runtime.h>
#include <cuda_bf16.h>
#include <cstdint>

// ---------------------------------------------------------------------------
// BitLinear: y = (quant(x) @ unpack(w)^T) * (amax/(127*ws)) + bias
// x: [4,4096,2048] f32  -> M = 16384, K = 2048, N = 2048, out f32
// Plain sm_103 target. R14 = R11 (best: mbarrier-decoupled 64/64 hybrid)
// with loader/compute roles SWAPPED: warps 4-7 (dp4a, under-utilized: 217us
// busy of 739) carry all cp.async loads + cons-waits; warps 0-3 (tensor,
// pacing class: 434us busy) are pure compute -- wait full[] (always ready),
// 64 ldsm + 64 IMMA, arrive cons. Tensor frags double-buffered (16 regs vs
// 24) so the pacing class has no spill (R11's alu=11.6% leak).
// ---------------------------------------------------------------------------

#define M_TOT 16384
#define N_TOT 2048
#define K_TOT 2048

#define TILE_M 128
#define TILE_N 128
#define TILE_KB 128                 // int8 K elements per pipeline stage
#define NCHUNK (K_TOT / TILE_KB)    // 16
#define NSTAGE 3
#define ROW_STRIDE 144              // 128B data + 16B pad: conflict-free
#define A_STAGE_BYTES (128 * ROW_STRIDE)      // 18432
#define STAGE_BYTES (2 * A_STAGE_BYTES)       // 36864
#define SMEM_BYTES (1024 + NSTAGE * STAGE_BYTES)  // 111616 -> 2 CTAs/SM

// -------------------------- scratch (device globals) -----------------------
__device__ __align__(128) int8_t g_xq[(size_t)M_TOT * K_TOT];  // 32 MiB
__device__ __align__(128) int8_t g_w[(size_t)N_TOT * K_TOT];   // 4 MiB
__device__ float g_rowscale[M_TOT];
__device__ int g_probe_sink;

// ------------------------------ PTX helpers --------------------------------
__device__ __forceinline__ uint32_t smem_u32(const void* p) {
    uint32_t a;
    asm("{ .reg .u64 t; cvta.to.shared.u64 t, %1; cvt.u32.u64 %0, t; }"
        : "=r"(a) : "l"(p));
    return a;
}

__device__ __forceinline__ void cpa16(uint32_t saddr, const void* gaddr) {
    asm volatile("cp.async.cg.shared.global [%0], [%1], 16;"
                 :: "r"(saddr), "l"(gaddr) : "memory");
}

#define MBARRIER_INIT(addr, cnt) \
    asm volatile("mbarrier.init.shared.b64 [%0], %1;" \
                 :: "r"((uint32_t)(addr)), "r"((uint32_t)(cnt)) : "memory")

#define MBARRIER_ARRIVE(addr) \
    asm volatile("mbarrier.arrive.shared.b64 _, [%0];" \
                 :: "r"((uint32_t)(addr)) : "memory")

#define CPASYNC_MBAR_ARRIVE(addr) \
    asm volatile("cp.async.mbarrier.arrive.noinc.shared.b64 [%0];" \
                 :: "r"((uint32_t)(addr)) : "memory")

#define MBARRIER_WAIT_PARITY(addr, ph) do {                                   \
    uint32_t _m = (uint32_t)(addr);                                           \
    uint32_t _p = (uint32_t)(ph);                                             \
    uint32_t _done;                                                           \
    asm volatile(                                                             \
        "{\n\t.reg .pred p;\n\t"                                              \
        "mbarrier.try_wait.parity.shared.b64 p, [%1], %2;\n\t"                \
        "selp.b32 %0, 1, 0, p;\n\t}"                                          \
        : "=r"(_done) : "r"(_m), "r"(_p) : "memory");                         \
    while (!_done) {                                                          \
        asm volatile(                                                         \
            "{\n\t.reg .pred p;\n\t"                                          \
            "mbarrier.try_wait.parity.shared.b64 p, [%1], %2, 0x989680;\n\t"  \
            "selp.b32 %0, 1, 0, p;\n\t}"                                      \
            : "=r"(_done) : "r"(_m), "r"(_p) : "memory");                     \
    }                                                                         \
} while (0)

__device__ __forceinline__ void ldsm4(uint32_t* r, uint32_t addr) {
    asm volatile("ldmatrix.sync.aligned.m8n8.x4.shared.b16 {%0,%1,%2,%3}, [%4];"
                 : "=r"(r[0]), "=r"(r[1]), "=r"(r[2]), "=r"(r[3]) : "r"(addr));
}

__device__ __forceinline__ void imma16832(int* c, const uint32_t* a,
                                          uint32_t b0, uint32_t b1) {
    asm volatile(
        "mma.sync.aligned.m16n8k32.row.col.s32.s8.s8.s32 "
        "{%0,%1,%2,%3}, {%4,%5,%6,%7}, {%8,%9}, {%0,%1,%2,%3};"
        : "+r"(c[0]), "+r"(c[1]), "+r"(c[2]), "+r"(c[3])
        : "r"(a[0]), "r"(a[1]), "r"(a[2]), "r"(a[3]), "r"(b0), "r"(b1));
}

__device__ __forceinline__ int dp4a(int a, int b, int c) {
    int d;
    asm("dp4a.s32.s32 %0, %1, %2, %3;" : "=r"(d) : "r"(a), "r"(b), "r"(c));
    return d;
}

// --------------------------- kernel 1: quantize ----------------------------
__device__ __forceinline__ int q1(float v, float sc) {
    float q = rintf(v * sc);                 // round half to even (matches jnp)
    q = fminf(fmaxf(q, -128.0f), 127.0f);
    return (int)q;
}

__device__ __forceinline__ int pack4(float4 v, float sc) {
    int q0 = q1(v.x, sc), q2 = q1(v.z, sc);
    int q1v = q1(v.y, sc), q3 = q1(v.w, sc);
    return (q0 & 255) | ((q1v & 255) << 8) | ((q2 & 255) << 16) | (q3 << 24);
}

__global__ __launch_bounds__(256) void quant_kernel(const float* __restrict__ x,
                                                    const float* __restrict__ wsp) {
    int r = blockIdx.x;
    int t = threadIdx.x;
    const float4* xr = reinterpret_cast<const float4*>(x + (size_t)r * K_TOT);
    float4 a = xr[t];
    float4 b = xr[t + 256];
    float am = fmaxf(fmaxf(fabsf(a.x), fabsf(a.y)), fmaxf(fabsf(a.z), fabsf(a.w)));
    am = fmaxf(am, fmaxf(fmaxf(fabsf(b.x), fabsf(b.y)), fmaxf(fabsf(b.z), fabsf(b.w))));
#pragma unroll
    for (int o = 16; o; o >>= 1) am = fmaxf(am, __shfl_xor_sync(0xffffffffu, am, o));
    __shared__ float red[8];
    __shared__ float s_amax;
    if ((t & 31) == 0) red[t >> 5] = am;
    __syncthreads();
    if (t == 0) {
        float m = red[0];
#pragma unroll
        for (int i = 1; i < 8; i++) m = fmaxf(m, red[i]);
        m = fmaxf(m, 1e-5f);
        s_amax = m;
        g_rowscale[r] = __fdiv_rn(m, 127.0f * wsp[0]);
    }
    __syncthreads();
    float sc = __fdiv_rn(127.0f, s_amax);
    int* dst = reinterpret_cast<int*>(g_xq + (size_t)r * K_TOT);
    dst[t]       = pack4(a, sc);
    dst[t + 256] = pack4(b, sc);
}

// ------------------------- kernel 2: unpack weights ------------------------
__global__ __launch_bounds__(256) void unpack_kernel(const int* __restrict__ wp) {
    int idx = blockIdx.x * 256 + threadIdx.x;      // 512*2048 entries
    int p = wp[idx];
    int d = idx & (K_TOT - 1);
    int rr = idx >> 11;
#pragma unroll
    for (int i = 0; i < 4; i++) {
        int w = ((p >> (2 * i)) & 3) - 1;
        g_w[((size_t)(i * 512 + rr) << 11) + d] = (int8_t)w;
    }
}

// ------------------------- probe (launch-slot filler) ----------------------
__global__ void probe_kernel() {
    if (threadIdx.x == 0) g_probe_sink = 1;
}

// ----------------------------- kernel 3: GEMM ------------------------------
// CTA 128x128, 256 threads, 2 CTAs/SM.
//   warps 0-3: IMMA N[0,64), 2x2 grid of 64Mx32N warp tiles. PURE compute.
//   warps 4-7: dp4a N[64,128), each 32M slab x 64N, thread 8Mx8N;
//              ALSO loaders (16 cpa16/thread/chunk) + cons-waits.
// Pipeline: 3 stages, full[s] (128 cp.async arrivals from warps 4-7),
// cons[s] (256 consumer arrivals). No __syncthreads in the mainloop.
__global__ __launch_bounds__(256, 2)
void gemm_kernel(const float* __restrict__ bias, float* __restrict__ out) {
    extern __shared__ char smem[];
    const uint32_t sb = smem_u32(smem);
    const uint32_t data_base = sb + 1024;
    const int tid = threadIdx.x;
    const int lane = tid & 31;
    const int wid = tid >> 5;
    const int m_base = blockIdx.y * TILE_M;
    const int n_base = blockIdx.x * TILE_N;

#define BAR_FULL(s) (sb + (uint32_t)(s) * 8)
#define BAR_CONS(s) (sb + 24 + (uint32_t)(s) * 8)
#define STAGE_AT(s) (data_base + (uint32_t)(s) * STAGE_BYTES)

    if (tid == 0) {
#pragma unroll
        for (int s = 0; s < NSTAGE; s++) {
            MBARRIER_INIT(BAR_FULL(s), 128);
            MBARRIER_INIT(BAR_CONS(s), 256);
        }
    }
    __syncthreads();   // one-time: mbarriers visible before use

    // ================= tensor-path state (warps 0-3) =================
    const int warp_m = wid & 1;          // 0..1 -> 64-row slab
    const int warp_n = (wid >> 1) & 1;   // 0..1 -> 32-col slab in N[0,64)
    const uint32_t a_rel = (uint32_t)((warp_m * 64 + (lane & 15)) * ROW_STRIDE
                                      + (lane >> 4) * 16);
    const uint32_t b_rel = (uint32_t)(A_STAGE_BYTES
                         + (warp_n * 32 + (lane & 7) + ((lane >> 4) & 1) * 8) * ROW_STRIDE
                         + ((lane >> 3) & 1) * 16);
    int acc[4][4][4];

    // ================= dp4a-path state (warps 4-7) ===================
    const int dw = wid - 4;              // 0..3 -> 32-row M slab
    const int tr = lane >> 3;            // 0..3
    const int tc = lane & 7;             // 0..7
    const uint32_t da_rel = (uint32_t)((dw * 32 + tr) * ROW_STRIDE);
    const uint32_t db_rel = (uint32_t)(A_STAGE_BYTES + (64 + tc) * ROW_STRIDE);
    int dacc[8][8];

    if (wid < 4) {
#pragma unroll
        for (int i = 0; i < 4; i++)
#pragma unroll
            for (int j = 0; j < 4; j++)
#pragma unroll
                for (int k = 0; k < 4; k++) acc[i][j][k] = 0;
    } else {
#pragma unroll
        for (int i = 0; i < 8; i++)
#pragma unroll
            for (int j = 0; j < 8; j++) dacc[i][j] = 0;
    }

    if (wid >= 4) {
        // ---- loader coordinates (warps 4-7): 16 cpa16 per chunk ----
        const int l_lr = (tid - 128) >> 3;           // 0..15
        const int l_lc = (tid & 7) * 16;             // byte col in 128B row
        const int8_t* l_ag = g_xq + (size_t)(m_base + l_lr) * K_TOT + l_lc;
        const int8_t* l_bg = g_w  + (size_t)(n_base + l_lr) * K_TOT + l_lc;
        const uint32_t l_sw = (uint32_t)(l_lr * ROW_STRIDE + l_lc);

        // ---- prologue: fill stages 0 and 1 (chunks 0 and 1) ----
#pragma unroll
        for (int s = 0; s < 2; s++) {
            uint32_t st = STAGE_AT(s);
            int koff = s * TILE_KB;
#pragma unroll
            for (int i = 0; i < 8; i++) {
                cpa16(st + l_sw + i * 16 * ROW_STRIDE,
                      l_ag + koff + (size_t)i * 16 * K_TOT);
                cpa16(st + A_STAGE_BYTES + l_sw + i * 16 * ROW_STRIDE,
                      l_bg + koff + (size_t)i * 16 * K_TOT);
            }
            CPASYNC_MBAR_ARRIVE(BAR_FULL(s));
        }

        // ---- mainloop: loader + dp4a compute ----
        for (int kc = 0; kc < NCHUNK; kc++) {
            const int s = kc % NSTAGE;
            const int u = kc / NSTAGE;

            const int kl = kc + 2;                 // chunk to load ahead
            if (kl < NCHUNK) {
                const int sl = kl % NSTAGE;
                const int ul = kl / NSTAGE;
                if (ul >= 1)                       // stage reuse: wait consumed
                    MBARRIER_WAIT_PARITY(BAR_CONS(sl), (ul - 1) & 1);
                uint32_t st = STAGE_AT(sl);
                int koff = kl * TILE_KB;
#pragma unroll
                for (int i = 0; i < 8; i++) {
                    cpa16(st + l_sw + i * 16 * ROW_STRIDE,
                          l_ag + koff + (size_t)i * 16 * K_TOT);
                    cpa16(st + A_STAGE_BYTES + l_sw + i * 16 * ROW_STRIDE,
                          l_bg + koff + (size_t)i * 16 * K_TOT);
                }
                CPASYNC_MBAR_ARRIVE(BAR_FULL(sl));
            }

            MBARRIER_WAIT_PARITY(BAR_FULL(s), u & 1);
            const uint32_t st = STAGE_AT(s);

#pragma unroll 4
            for (int g = 0; g < 16; g++) {
                const uint32_t kb = (uint32_t)(g * 8);
                int2 av[8], bv[8];
#pragma unroll
                for (int mt = 0; mt < 8; mt++) {
                    uint32_t ad = st + da_rel + (uint32_t)(mt * 4 * ROW_STRIDE) + kb;
                    asm volatile("ld.shared.v2.b32 {%0,%1}, [%2];"
                                 : "=r"(av[mt].x), "=r"(av[mt].y) : "r"(ad));
                }
#pragma unroll
                for (int nt = 0; nt < 8; nt++) {
                    uint32_t bd = st + db_rel + (uint32_t)(nt * 8 * ROW_STRIDE) + kb;
                    asm volatile("ld.shared.v2.b32 {%0,%1}, [%2];"
                                 : "=r"(bv[nt].x), "=r"(bv[nt].y) : "r"(bd));
                }
#pragma unroll
                for (int mt = 0; mt < 8; mt++) {
#pragma unroll
                    for (int nt = 0; nt < 8; nt++) {
                        int c = dp4a(av[mt].x, bv[nt].x, dacc[mt][nt]);
                        dacc[mt][nt] = dp4a(av[mt].y, bv[nt].y, c);
                    }
                }
            }
            MBARRIER_ARRIVE(BAR_CONS(s));
        }
    } else {
        // ---- mainloop: pure tensor compute (warps 0-3) ----
        for (int kc = 0; kc < NCHUNK; kc++) {
            const int s = kc % NSTAGE;
            const int u = kc / NSTAGE;

            MBARRIER_WAIT_PARITY(BAR_FULL(s), u & 1);
            const uint32_t st = STAGE_AT(s);

#pragma unroll
            for (int kk = 0; kk < 4; kk++) {
                uint32_t b[2][4];
#pragma unroll
                for (int p = 0; p < 2; p++)
                    ldsm4(b[p], st + b_rel + (uint32_t)(p * 16 * ROW_STRIDE + kk * 32));
                uint32_t afr[2][4];
                ldsm4(afr[0], st + a_rel + (uint32_t)(kk * 32));
#pragma unroll
                for (int mt = 0; mt < 4; mt++) {
                    if (mt < 3)
                        ldsm4(afr[(mt + 1) & 1],
                              st + a_rel + (uint32_t)((mt + 1) * 16 * ROW_STRIDE + kk * 32));
                    const int cur = mt & 1;
#pragma unroll
                    for (int nt = 0; nt < 4; nt++) {
                        imma16832(acc[mt][nt], afr[cur], b[nt >> 1][(nt & 1) * 2],
                                  b[nt >> 1][(nt & 1) * 2 + 1]);
                    }
                }
            }
            MBARRIER_ARRIVE(BAR_CONS(s));
        }
    }

    // ------------------------------ epilogue -------------------------------
    if (wid < 4) {
        float rs0[4], rs1[4];
#pragma unroll
        for (int mt = 0; mt < 4; mt++) {
            int m = m_base + warp_m * 64 + mt * 16 + (lane >> 2);
            rs0[mt] = g_rowscale[m];
            rs1[mt] = g_rowscale[m + 8];
        }
#pragma unroll
        for (int nt = 0; nt < 4; nt++) {
            int n = n_base + warp_n * 32 + nt * 8 + 2 * (lane & 3);
            float2 bv2 = *reinterpret_cast<const float2*>(bias + n);
#pragma unroll
            for (int mt = 0; mt < 4; mt++) {
                int m = m_base + warp_m * 64 + mt * 16 + (lane >> 2);
                float2 v0, v1;
                v0.x = __int2float_rn(acc[mt][nt][0]) * rs0[mt] + bv2.x;
                v0.y = __int2float_rn(acc[mt][nt][1]) * rs0[mt] + bv2.y;
                v1.x = __int2float_rn(acc[mt][nt][2]) * rs1[mt] + bv2.x;
                v1.y = __int2float_rn(acc[mt][nt][3]) * rs1[mt] + bv2.y;
                *reinterpret_cast<float2*>(out + (size_t)m * N_TOT + n) = v0;
                *reinterpret_cast<float2*>(out + (size_t)(m + 8) * N_TOT + n) = v1;
            }
        }
    } else {
        float rs[8];
#pragma unroll
        for (int mt = 0; mt < 8; mt++)
            rs[mt] = g_rowscale[m_base + dw * 32 + mt * 4 + tr];
#pragma unroll
        for (int nt = 0; nt < 8; nt++) {
            int n = n_base + 64 + nt * 8 + tc;
            float bvv = bias[n];
#pragma unroll
            for (int mt = 0; mt < 8; mt++) {
                int m = m_base + dw * 32 + mt * 4 + tr;
                out[(size_t)m * N_TOT + n] =
                    __int2float_rn(dacc[mt][nt]) * rs[mt] + bvv;
            }
        }
    }
}

// ------------------------------- launcher ----------------------------------
extern "C" void kernel_launch(void* const* d_in, const int* in_sizes, int n_in,
                              void* d_out, int out_size) {
    const float* x    = (const float*)d_in[0];
    const int*   wp   = (const int*)d_in[1];
    const float* ws   = (const float*)d_in[2];
    const float* bias = (const float*)d_in[3];
    float*       out  = (float*)d_out;

    (void)in_sizes; (void)n_in; (void)out_size;

    static bool attr_set = false;
    if (!attr_set) {
        cudaFuncSetAttribute(gemm_kernel, cudaFuncAttributeMaxDynamicSharedMemorySize,
                             SMEM_BYTES);
        attr_set = true;
    }

    // Launch order keeps gemm at absolute launch #6 for ncu (-s 5 -c 1).
    unpack_kernel<<<(512 * K_TOT) / 256, 256>>>(wp);
    quant_kernel<<<M_TOT, 256>>>(x, ws);
    probe_kernel<<<1, 32>>>();
    dim3 grid(N_TOT / TILE_N, M_TOT / TILE_M);
    gemm_kernel<<<grid, 256, SMEM_BYTES>>>(bias, out);
}

// round 15
// speedup vs baseline: 1.2958x; 1.0053x over previous
#include <cuda_runtime.h>
#include <cuda_bf16.h>
#include <cstdint>

// ---------------------------------------------------------------------------
// BitLinear: y = (quant(x) @ unpack(w)^T) * (amax/(127*ws)) + bias
// x: [4,4096,2048] f32  -> M = 16384, K = 2048, N = 2048, out f32
// Plain sm_103 target. R15 = R14 (653.7us: warp-specialized mbarrier
// pipeline, tensor warps pure IMMA N[0,64), dp4a warps compute+load
// N[64,128)) with two changes:
//   1. tensor loop: B fragments double-buffered ACROSS kk (B-ldsm for kk+1
//      issued under the 16 IMMAs of kk) -- removes per-kk exposed ldsm head.
//   2. dp4a loop: B operands loaded in two batches of 4 (reg relief on the
//      class that pins regs=128).
// ---------------------------------------------------------------------------

#define M_TOT 16384
#define N_TOT 2048
#define K_TOT 2048

#define TILE_M 128
#define TILE_N 128
#define TILE_KB 128                 // int8 K elements per pipeline stage
#define NCHUNK (K_TOT / TILE_KB)    // 16
#define NSTAGE 3
#define ROW_STRIDE 144              // 128B data + 16B pad: conflict-free
#define A_STAGE_BYTES (128 * ROW_STRIDE)      // 18432
#define STAGE_BYTES (2 * A_STAGE_BYTES)       // 36864
#define SMEM_BYTES (1024 + NSTAGE * STAGE_BYTES)  // 111616 -> 2 CTAs/SM

// -------------------------- scratch (device globals) -----------------------
__device__ __align__(128) int8_t g_xq[(size_t)M_TOT * K_TOT];  // 32 MiB
__device__ __align__(128) int8_t g_w[(size_t)N_TOT * K_TOT];   // 4 MiB
__device__ float g_rowscale[M_TOT];
__device__ int g_probe_sink;

// ------------------------------ PTX helpers --------------------------------
__device__ __forceinline__ uint32_t smem_u32(const void* p) {
    uint32_t a;
    asm("{ .reg .u64 t; cvta.to.shared.u64 t, %1; cvt.u32.u64 %0, t; }"
        : "=r"(a) : "l"(p));
    return a;
}

__device__ __forceinline__ void cpa16(uint32_t saddr, const void* gaddr) {
    asm volatile("cp.async.cg.shared.global [%0], [%1], 16;"
                 :: "r"(saddr), "l"(gaddr) : "memory");
}

#define MBARRIER_INIT(addr, cnt) \
    asm volatile("mbarrier.init.shared.b64 [%0], %1;" \
                 :: "r"((uint32_t)(addr)), "r"((uint32_t)(cnt)) : "memory")

#define MBARRIER_ARRIVE(addr) \
    asm volatile("mbarrier.arrive.shared.b64 _, [%0];" \
                 :: "r"((uint32_t)(addr)) : "memory")

#define CPASYNC_MBAR_ARRIVE(addr) \
    asm volatile("cp.async.mbarrier.arrive.noinc.shared.b64 [%0];" \
                 :: "r"((uint32_t)(addr)) : "memory")

#define MBARRIER_WAIT_PARITY(addr, ph) do {                                   \
    uint32_t _m = (uint32_t)(addr);                                           \
    uint32_t _p = (uint32_t)(ph);                                             \
    uint32_t _done;                                                           \
    asm volatile(                                                             \
        "{\n\t.reg .pred p;\n\t"                                              \
        "mbarrier.try_wait.parity.shared.b64 p, [%1], %2;\n\t"                \
        "selp.b32 %0, 1, 0, p;\n\t}"                                          \
        : "=r"(_done) : "r"(_m), "r"(_p) : "memory");                         \
    while (!_done) {                                                          \
        asm volatile(                                                         \
            "{\n\t.reg .pred p;\n\t"                                          \
            "mbarrier.try_wait.parity.shared.b64 p, [%1], %2, 0x989680;\n\t"  \
            "selp.b32 %0, 1, 0, p;\n\t}"                                      \
            : "=r"(_done) : "r"(_m), "r"(_p) : "memory");                     \
    }                                                                         \
} while (0)

__device__ __forceinline__ void ldsm4(uint32_t* r, uint32_t addr) {
    asm volatile("ldmatrix.sync.aligned.m8n8.x4.shared.b16 {%0,%1,%2,%3}, [%4];"
                 : "=r"(r[0]), "=r"(r[1]), "=r"(r[2]), "=r"(r[3]) : "r"(addr));
}

__device__ __forceinline__ void imma16832(int* c, const uint32_t* a,
                                          uint32_t b0, uint32_t b1) {
    asm volatile(
        "mma.sync.aligned.m16n8k32.row.col.s32.s8.s8.s32 "
        "{%0,%1,%2,%3}, {%4,%5,%6,%7}, {%8,%9}, {%0,%1,%2,%3};"
        : "+r"(c[0]), "+r"(c[1]), "+r"(c[2]), "+r"(c[3])
        : "r"(a[0]), "r"(a[1]), "r"(a[2]), "r"(a[3]), "r"(b0), "r"(b1));
}

__device__ __forceinline__ int dp4a(int a, int b, int c) {
    int d;
    asm("dp4a.s32.s32 %0, %1, %2, %3;" : "=r"(d) : "r"(a), "r"(b), "r"(c));
    return d;
}

// --------------------------- kernel 1: quantize ----------------------------
__device__ __forceinline__ int q1(float v, float sc) {
    float q = rintf(v * sc);                 // round half to even (matches jnp)
    q = fminf(fmaxf(q, -128.0f), 127.0f);
    return (int)q;
}

__device__ __forceinline__ int pack4(float4 v, float sc) {
    int q0 = q1(v.x, sc), q2 = q1(v.z, sc);
    int q1v = q1(v.y, sc), q3 = q1(v.w, sc);
    return (q0 & 255) | ((q1v & 255) << 8) | ((q2 & 255) << 16) | (q3 << 24);
}

__global__ __launch_bounds__(256) void quant_kernel(const float* __restrict__ x,
                                                    const float* __restrict__ wsp) {
    int r = blockIdx.x;
    int t = threadIdx.x;
    const float4* xr = reinterpret_cast<const float4*>(x + (size_t)r * K_TOT);
    float4 a = xr[t];
    float4 b = xr[t + 256];
    float am = fmaxf(fmaxf(fabsf(a.x), fabsf(a.y)), fmaxf(fabsf(a.z), fabsf(a.w)));
    am = fmaxf(am, fmaxf(fmaxf(fabsf(b.x), fabsf(b.y)), fmaxf(fabsf(b.z), fabsf(b.w))));
#pragma unroll
    for (int o = 16; o; o >>= 1) am = fmaxf(am, __shfl_xor_sync(0xffffffffu, am, o));
    __shared__ float red[8];
    __shared__ float s_amax;
    if ((t & 31) == 0) red[t >> 5] = am;
    __syncthreads();
    if (t == 0) {
        float m = red[0];
#pragma unroll
        for (int i = 1; i < 8; i++) m = fmaxf(m, red[i]);
        m = fmaxf(m, 1e-5f);
        s_amax = m;
        g_rowscale[r] = __fdiv_rn(m, 127.0f * wsp[0]);
    }
    __syncthreads();
    float sc = __fdiv_rn(127.0f, s_amax);
    int* dst = reinterpret_cast<int*>(g_xq + (size_t)r * K_TOT);
    dst[t]       = pack4(a, sc);
    dst[t + 256] = pack4(b, sc);
}

// ------------------------- kernel 2: unpack weights ------------------------
__global__ __launch_bounds__(256) void unpack_kernel(const int* __restrict__ wp) {
    int idx = blockIdx.x * 256 + threadIdx.x;      // 512*2048 entries
    int p = wp[idx];
    int d = idx & (K_TOT - 1);
    int rr = idx >> 11;
#pragma unroll
    for (int i = 0; i < 4; i++) {
        int w = ((p >> (2 * i)) & 3) - 1;
        g_w[((size_t)(i * 512 + rr) << 11) + d] = (int8_t)w;
    }
}

// ------------------------- probe (launch-slot filler) ----------------------
__global__ void probe_kernel() {
    if (threadIdx.x == 0) g_probe_sink = 1;
}

// ----------------------------- kernel 3: GEMM ------------------------------
// CTA 128x128, 256 threads, 2 CTAs/SM.
//   warps 0-3: IMMA N[0,64), 2x2 grid of 64Mx32N warp tiles. PURE compute,
//              B frags double-buffered across kk.
//   warps 4-7: dp4a N[64,128), each 32M slab x 64N, thread 8Mx8N;
//              ALSO loaders (16 cpa16/thread/chunk) + cons-waits.
// Pipeline: 3 stages, full[s] (128 cp.async arrivals from warps 4-7),
// cons[s] (256 consumer arrivals). No __syncthreads in the mainloop.
__global__ __launch_bounds__(256, 2)
void gemm_kernel(const float* __restrict__ bias, float* __restrict__ out) {
    extern __shared__ char smem[];
    const uint32_t sb = smem_u32(smem);
    const uint32_t data_base = sb + 1024;
    const int tid = threadIdx.x;
    const int lane = tid & 31;
    const int wid = tid >> 5;
    const int m_base = blockIdx.y * TILE_M;
    const int n_base = blockIdx.x * TILE_N;

#define BAR_FULL(s) (sb + (uint32_t)(s) * 8)
#define BAR_CONS(s) (sb + 24 + (uint32_t)(s) * 8)
#define STAGE_AT(s) (data_base + (uint32_t)(s) * STAGE_BYTES)

    if (tid == 0) {
#pragma unroll
        for (int s = 0; s < NSTAGE; s++) {
            MBARRIER_INIT(BAR_FULL(s), 128);
            MBARRIER_INIT(BAR_CONS(s), 256);
        }
    }
    __syncthreads();   // one-time: mbarriers visible before use

    // ================= tensor-path state (warps 0-3) =================
    const int warp_m = wid & 1;          // 0..1 -> 64-row slab
    const int warp_n = (wid >> 1) & 1;   // 0..1 -> 32-col slab in N[0,64)
    const uint32_t a_rel = (uint32_t)((warp_m * 64 + (lane & 15)) * ROW_STRIDE
                                      + (lane >> 4) * 16);
    const uint32_t b_rel = (uint32_t)(A_STAGE_BYTES
                         + (warp_n * 32 + (lane & 7) + ((lane >> 4) & 1) * 8) * ROW_STRIDE
                         + ((lane >> 3) & 1) * 16);
    int acc[4][4][4];

    // ================= dp4a-path state (warps 4-7) ===================
    const int dw = wid - 4;              // 0..3 -> 32-row M slab
    const int tr = lane >> 3;            // 0..3
    const int tc = lane & 7;             // 0..7
    const uint32_t da_rel = (uint32_t)((dw * 32 + tr) * ROW_STRIDE);
    const uint32_t db_rel = (uint32_t)(A_STAGE_BYTES + (64 + tc) * ROW_STRIDE);
    int dacc[8][8];

    if (wid < 4) {
#pragma unroll
        for (int i = 0; i < 4; i++)
#pragma unroll
            for (int j = 0; j < 4; j++)
#pragma unroll
                for (int k = 0; k < 4; k++) acc[i][j][k] = 0;
    } else {
#pragma unroll
        for (int i = 0; i < 8; i++)
#pragma unroll
            for (int j = 0; j < 8; j++) dacc[i][j] = 0;
    }

    if (wid >= 4) {
        // ---- loader coordinates (warps 4-7): 16 cpa16 per chunk ----
        const int l_lr = (tid - 128) >> 3;           // 0..15
        const int l_lc = (tid & 7) * 16;             // byte col in 128B row
        const int8_t* l_ag = g_xq + (size_t)(m_base + l_lr) * K_TOT + l_lc;
        const int8_t* l_bg = g_w  + (size_t)(n_base + l_lr) * K_TOT + l_lc;
        const uint32_t l_sw = (uint32_t)(l_lr * ROW_STRIDE + l_lc);

        // ---- prologue: fill stages 0 and 1 (chunks 0 and 1) ----
#pragma unroll
        for (int s = 0; s < 2; s++) {
            uint32_t st = STAGE_AT(s);
            int koff = s * TILE_KB;
#pragma unroll
            for (int i = 0; i < 8; i++) {
                cpa16(st + l_sw + i * 16 * ROW_STRIDE,
                      l_ag + koff + (size_t)i * 16 * K_TOT);
                cpa16(st + A_STAGE_BYTES + l_sw + i * 16 * ROW_STRIDE,
                      l_bg + koff + (size_t)i * 16 * K_TOT);
            }
            CPASYNC_MBAR_ARRIVE(BAR_FULL(s));
        }

        // ---- mainloop: loader + dp4a compute ----
        for (int kc = 0; kc < NCHUNK; kc++) {
            const int s = kc % NSTAGE;
            const int u = kc / NSTAGE;

            const int kl = kc + 2;                 // chunk to load ahead
            if (kl < NCHUNK) {
                const int sl = kl % NSTAGE;
                const int ul = kl / NSTAGE;
                if (ul >= 1)                       // stage reuse: wait consumed
                    MBARRIER_WAIT_PARITY(BAR_CONS(sl), (ul - 1) & 1);
                uint32_t st = STAGE_AT(sl);
                int koff = kl * TILE_KB;
#pragma unroll
                for (int i = 0; i < 8; i++) {
                    cpa16(st + l_sw + i * 16 * ROW_STRIDE,
                          l_ag + koff + (size_t)i * 16 * K_TOT);
                    cpa16(st + A_STAGE_BYTES + l_sw + i * 16 * ROW_STRIDE,
                          l_bg + koff + (size_t)i * 16 * K_TOT);
                }
                CPASYNC_MBAR_ARRIVE(BAR_FULL(sl));
            }

            MBARRIER_WAIT_PARITY(BAR_FULL(s), u & 1);
            const uint32_t st = STAGE_AT(s);

#pragma unroll 4
            for (int g = 0; g < 16; g++) {
                const uint32_t kb = (uint32_t)(g * 8);
                int2 av[8];
#pragma unroll
                for (int mt = 0; mt < 8; mt++) {
                    uint32_t ad = st + da_rel + (uint32_t)(mt * 4 * ROW_STRIDE) + kb;
                    asm volatile("ld.shared.v2.b32 {%0,%1}, [%2];"
                                 : "=r"(av[mt].x), "=r"(av[mt].y) : "r"(ad));
                }
#pragma unroll
                for (int half = 0; half < 2; half++) {
                    int2 bv[4];
#pragma unroll
                    for (int j = 0; j < 4; j++) {
                        uint32_t bd = st + db_rel
                            + (uint32_t)((half * 4 + j) * 8 * ROW_STRIDE) + kb;
                        asm volatile("ld.shared.v2.b32 {%0,%1}, [%2];"
                                     : "=r"(bv[j].x), "=r"(bv[j].y) : "r"(bd));
                    }
#pragma unroll
                    for (int j = 0; j < 4; j++) {
                        const int nt = half * 4 + j;
#pragma unroll
                        for (int mt = 0; mt < 8; mt++) {
                            int c = dp4a(av[mt].x, bv[j].x, dacc[mt][nt]);
                            dacc[mt][nt] = dp4a(av[mt].y, bv[j].y, c);
                        }
                    }
                }
            }
            MBARRIER_ARRIVE(BAR_CONS(s));
        }
    } else {
        // ---- mainloop: pure tensor compute (warps 0-3) ----
        for (int kc = 0; kc < NCHUNK; kc++) {
            const int s = kc % NSTAGE;
            const int u = kc / NSTAGE;

            MBARRIER_WAIT_PARITY(BAR_FULL(s), u & 1);
            const uint32_t st = STAGE_AT(s);

            // B double-buffered across kk: preload kk=0, prefetch kk+1
            // under the IMMAs of kk.
            uint32_t b[2][2][4];                   // [buf][p][frag]
#pragma unroll
            for (int p = 0; p < 2; p++)
                ldsm4(b[0][p], st + b_rel + (uint32_t)(p * 16 * ROW_STRIDE));

#pragma unroll
            for (int kk = 0; kk < 4; kk++) {
                const int cur = kk & 1, nxt = cur ^ 1;
                if (kk < 3) {
#pragma unroll
                    for (int p = 0; p < 2; p++)
                        ldsm4(b[nxt][p],
                              st + b_rel + (uint32_t)(p * 16 * ROW_STRIDE + (kk + 1) * 32));
                }
                uint32_t afr[2][4];
                ldsm4(afr[0], st + a_rel + (uint32_t)(kk * 32));
#pragma unroll
                for (int mt = 0; mt < 4; mt++) {
                    if (mt < 3)
                        ldsm4(afr[(mt + 1) & 1],
                              st + a_rel + (uint32_t)((mt + 1) * 16 * ROW_STRIDE + kk * 32));
                    const int ab = mt & 1;
#pragma unroll
                    for (int nt = 0; nt < 4; nt++) {
                        imma16832(acc[mt][nt], afr[ab], b[cur][nt >> 1][(nt & 1) * 2],
                                  b[cur][nt >> 1][(nt & 1) * 2 + 1]);
                    }
                }
            }
            MBARRIER_ARRIVE(BAR_CONS(s));
        }
    }

    // ------------------------------ epilogue -------------------------------
    if (wid < 4) {
        float rs0[4], rs1[4];
#pragma unroll
        for (int mt = 0; mt < 4; mt++) {
            int m = m_base + warp_m * 64 + mt * 16 + (lane >> 2);
            rs0[mt] = g_rowscale[m];
            rs1[mt] = g_rowscale[m + 8];
        }
#pragma unroll
        for (int nt = 0; nt < 4; nt++) {
            int n = n_base + warp_n * 32 + nt * 8 + 2 * (lane & 3);
            float2 bv2 = *reinterpret_cast<const float2*>(bias + n);
#pragma unroll
            for (int mt = 0; mt < 4; mt++) {
                int m = m_base + warp_m * 64 + mt * 16 + (lane >> 2);
                float2 v0, v1;
                v0.x = __int2float_rn(acc[mt][nt][0]) * rs0[mt] + bv2.x;
                v0.y = __int2float_rn(acc[mt][nt][1]) * rs0[mt] + bv2.y;
                v1.x = __int2float_rn(acc[mt][nt][2]) * rs1[mt] + bv2.x;
                v1.y = __int2float_rn(acc[mt][nt][3]) * rs1[mt] + bv2.y;
                *reinterpret_cast<float2*>(out + (size_t)m * N_TOT + n) = v0;
                *reinterpret_cast<float2*>(out + (size_t)(m + 8) * N_TOT + n) = v1;
            }
        }
    } else {
        float rs[8];
#pragma unroll
        for (int mt = 0; mt < 8; mt++)
            rs[mt] = g_rowscale[m_base + dw * 32 + mt * 4 + tr];
#pragma unroll
        for (int nt = 0; nt < 8; nt++) {
            int n = n_base + 64 + nt * 8 + tc;
            float bvv = bias[n];
#pragma unroll
            for (int mt = 0; mt < 8; mt++) {
                int m = m_base + dw * 32 + mt * 4 + tr;
                out[(size_t)m * N_TOT + n] =
                    __int2float_rn(dacc[mt][nt]) * rs[mt] + bvv;
            }
        }
    }
}

// ------------------------------- launcher ----------------------------------
extern "C" void kernel_launch(void* const* d_in, const int* in_sizes, int n_in,
                              void* d_out, int out_size) {
    const float* x    = (const float*)d_in[0];
    const int*   wp   = (const int*)d_in[1];
    const float* ws   = (const float*)d_in[2];
    const float* bias = (const float*)d_in[3];
    float*       out  = (float*)d_out;

    (void)in_sizes; (void)n_in; (void)out_size;

    static bool attr_set = false;
    if (!attr_set) {
        cudaFuncSetAttribute(gemm_kernel, cudaFuncAttributeMaxDynamicSharedMemorySize,
                             SMEM_BYTES);
        attr_set = true;
    }

    // Launch order keeps gemm at absolute launch #6 for ncu (-s 5 -c 1).
    unpack_kernel<<<(512 * K_TOT) / 256, 256>>>(wp);
    quant_kernel<<<M_TOT, 256>>>(x, ws);
    probe_kernel<<<1, 32>>>();
    dim3 grid(N_TOT / TILE_N, M_TOT / TILE_M);
    gemm_kernel<<<grid, 256, SMEM_BYTES>>>(bias, out);
}

// round 16
// speedup vs baseline: 1.3003x; 1.0035x over previous
#include <cuda_runtime.h>
#include <cuda_bf16.h>
#include <cstdint>

// ---------------------------------------------------------------------------
// BitLinear: y = (quant(x) @ unpack(w)^T) * (amax/(127*ws)) + bias
// x: [4,4096,2048] f32  -> M = 16384, K = 2048, N = 2048, out f32
// Plain sm_103 target. R16 = R15 with warp classes SWAPPED to exploit the
// hi-wid-first SMSP arbiter: tensor (IMMA, sparse pipe-paced issue) on
// wid 4-7 (HIGH priority), dp4a+loader (rt=1 dense issue) on wid 0-3 (fills
// leftover slots). R15's 29% tensor-pipe idle is modeled as IMMA-queue
// starvation during 128-long dp4a issue bursts that outranked tensor warps.
// Also: unpack fused into quant launch (one fewer kernel).
// ---------------------------------------------------------------------------

#define M_TOT 16384
#define N_TOT 2048
#define K_TOT 2048

#define TILE_M 128
#define TILE_N 128
#define TILE_KB 128                 // int8 K elements per pipeline stage
#define NCHUNK (K_TOT / TILE_KB)    // 16
#define NSTAGE 3
#define ROW_STRIDE 144              // 128B data + 16B pad: conflict-free
#define A_STAGE_BYTES (128 * ROW_STRIDE)      // 18432
#define STAGE_BYTES (2 * A_STAGE_BYTES)       // 36864
#define SMEM_BYTES (1024 + NSTAGE * STAGE_BYTES)  // 111616 -> 2 CTAs/SM

// -------------------------- scratch (device globals) -----------------------
__device__ __align__(128) int8_t g_xq[(size_t)M_TOT * K_TOT];  // 32 MiB
__device__ __align__(128) int8_t g_w[(size_t)N_TOT * K_TOT];   // 4 MiB
__device__ float g_rowscale[M_TOT];
__device__ int g_probe_sink;

// ------------------------------ PTX helpers --------------------------------
__device__ __forceinline__ uint32_t smem_u32(const void* p) {
    uint32_t a;
    asm("{ .reg .u64 t; cvta.to.shared.u64 t, %1; cvt.u32.u64 %0, t; }"
        : "=r"(a) : "l"(p));
    return a;
}

__device__ __forceinline__ void cpa16(uint32_t saddr, const void* gaddr) {
    asm volatile("cp.async.cg.shared.global [%0], [%1], 16;"
                 :: "r"(saddr), "l"(gaddr) : "memory");
}

#define MBARRIER_INIT(addr, cnt) \
    asm volatile("mbarrier.init.shared.b64 [%0], %1;" \
                 :: "r"((uint32_t)(addr)), "r"((uint32_t)(cnt)) : "memory")

#define MBARRIER_ARRIVE(addr) \
    asm volatile("mbarrier.arrive.shared.b64 _, [%0];" \
                 :: "r"((uint32_t)(addr)) : "memory")

#define CPASYNC_MBAR_ARRIVE(addr) \
    asm volatile("cp.async.mbarrier.arrive.noinc.shared.b64 [%0];" \
                 :: "r"((uint32_t)(addr)) : "memory")

#define MBARRIER_WAIT_PARITY(addr, ph) do {                                   \
    uint32_t _m = (uint32_t)(addr);                                           \
    uint32_t _p = (uint32_t)(ph);                                             \
    uint32_t _done;                                                           \
    asm volatile(                                                             \
        "{\n\t.reg .pred p;\n\t"                                              \
        "mbarrier.try_wait.parity.shared.b64 p, [%1], %2;\n\t"                \
        "selp.b32 %0, 1, 0, p;\n\t}"                                          \
        : "=r"(_done) : "r"(_m), "r"(_p) : "memory");                         \
    while (!_done) {                                                          \
        asm volatile(                                                         \
            "{\n\t.reg .pred p;\n\t"                                          \
            "mbarrier.try_wait.parity.shared.b64 p, [%1], %2, 0x989680;\n\t"  \
            "selp.b32 %0, 1, 0, p;\n\t}"                                      \
            : "=r"(_done) : "r"(_m), "r"(_p) : "memory");                     \
    }                                                                         \
} while (0)

__device__ __forceinline__ void ldsm4(uint32_t* r, uint32_t addr) {
    asm volatile("ldmatrix.sync.aligned.m8n8.x4.shared.b16 {%0,%1,%2,%3}, [%4];"
                 : "=r"(r[0]), "=r"(r[1]), "=r"(r[2]), "=r"(r[3]) : "r"(addr));
}

__device__ __forceinline__ void imma16832(int* c, const uint32_t* a,
                                          uint32_t b0, uint32_t b1) {
    asm volatile(
        "mma.sync.aligned.m16n8k32.row.col.s32.s8.s8.s32 "
        "{%0,%1,%2,%3}, {%4,%5,%6,%7}, {%8,%9}, {%0,%1,%2,%3};"
        : "+r"(c[0]), "+r"(c[1]), "+r"(c[2]), "+r"(c[3])
        : "r"(a[0]), "r"(a[1]), "r"(a[2]), "r"(a[3]), "r"(b0), "r"(b1));
}

__device__ __forceinline__ int dp4a(int a, int b, int c) {
    int d;
    asm("dp4a.s32.s32 %0, %1, %2, %3;" : "=r"(d) : "r"(a), "r"(b), "r"(c));
    return d;
}

// ------------------- kernel 1: quantize + unpack (fused) -------------------
__device__ __forceinline__ int q1(float v, float sc) {
    float q = rintf(v * sc);                 // round half to even (matches jnp)
    q = fminf(fmaxf(q, -128.0f), 127.0f);
    return (int)q;
}

__device__ __forceinline__ int pack4(float4 v, float sc) {
    int q0 = q1(v.x, sc), q2 = q1(v.z, sc);
    int q1v = q1(v.y, sc), q3 = q1(v.w, sc);
    return (q0 & 255) | ((q1v & 255) << 8) | ((q2 & 255) << 16) | (q3 << 24);
}

__global__ __launch_bounds__(256) void prep_kernel(const float* __restrict__ x,
                                                   const float* __restrict__ wsp,
                                                   const int* __restrict__ wp) {
    if (blockIdx.x >= M_TOT) {
        // ---- unpack part: blocks [M_TOT, M_TOT+4096) ----
        int idx = (blockIdx.x - M_TOT) * 256 + threadIdx.x;  // 512*2048 entries
        int p = wp[idx];
        int d = idx & (K_TOT - 1);
        int rr = idx >> 11;
#pragma unroll
        for (int i = 0; i < 4; i++) {
            int w = ((p >> (2 * i)) & 3) - 1;
            g_w[((size_t)(i * 512 + rr) << 11) + d] = (int8_t)w;
        }
        return;
    }
    // ---- quant part: blocks [0, M_TOT) ----
    int r = blockIdx.x;
    int t = threadIdx.x;
    const float4* xr = reinterpret_cast<const float4*>(x + (size_t)r * K_TOT);
    float4 a = xr[t];
    float4 b = xr[t + 256];
    float am = fmaxf(fmaxf(fabsf(a.x), fabsf(a.y)), fmaxf(fabsf(a.z), fabsf(a.w)));
    am = fmaxf(am, fmaxf(fmaxf(fabsf(b.x), fabsf(b.y)), fmaxf(fabsf(b.z), fabsf(b.w))));
#pragma unroll
    for (int o = 16; o; o >>= 1) am = fmaxf(am, __shfl_xor_sync(0xffffffffu, am, o));
    __shared__ float red[8];
    __shared__ float s_amax;
    if ((t & 31) == 0) red[t >> 5] = am;
    __syncthreads();
    if (t == 0) {
        float m = red[0];
#pragma unroll
        for (int i = 1; i < 8; i++) m = fmaxf(m, red[i]);
        m = fmaxf(m, 1e-5f);
        s_amax = m;
        g_rowscale[r] = __fdiv_rn(m, 127.0f * wsp[0]);
    }
    __syncthreads();
    float sc = __fdiv_rn(127.0f, s_amax);
    int* dst = reinterpret_cast<int*>(g_xq + (size_t)r * K_TOT);
    dst[t]       = pack4(a, sc);
    dst[t + 256] = pack4(b, sc);
}

// ------------------------- probe (launch-slot filler) ----------------------
__global__ void probe_kernel() {
    if (threadIdx.x == 0) g_probe_sink = 1;
}

// ----------------------------- kernel 3: GEMM ------------------------------
// CTA 128x128, 256 threads, 2 CTAs/SM.
//   warps 4-7 (HI arbiter priority): IMMA N[0,64), 2x2 of 64Mx32N. PURE
//              compute, B frags double-buffered across kk.
//   warps 0-3 (LO priority): dp4a N[64,128), each 32M slab x 64N, thread
//              8Mx8N; ALSO loaders (16 cpa16/thread/chunk) + cons-waits.
// Pipeline: 3 stages, full[s] (128 cp.async arrivals from warps 0-3),
// cons[s] (256 consumer arrivals). No __syncthreads in the mainloop.
__global__ __launch_bounds__(256, 2)
void gemm_kernel(const float* __restrict__ bias, float* __restrict__ out) {
    extern __shared__ char smem[];
    const uint32_t sb = smem_u32(smem);
    const uint32_t data_base = sb + 1024;
    const int tid = threadIdx.x;
    const int lane = tid & 31;
    const int wid = tid >> 5;
    const int m_base = blockIdx.y * TILE_M;
    const int n_base = blockIdx.x * TILE_N;

#define BAR_FULL(s) (sb + (uint32_t)(s) * 8)
#define BAR_CONS(s) (sb + 24 + (uint32_t)(s) * 8)
#define STAGE_AT(s) (data_base + (uint32_t)(s) * STAGE_BYTES)

    if (tid == 0) {
#pragma unroll
        for (int s = 0; s < NSTAGE; s++) {
            MBARRIER_INIT(BAR_FULL(s), 128);
            MBARRIER_INIT(BAR_CONS(s), 256);
        }
    }
    __syncthreads();   // one-time: mbarriers visible before use

    // ================= tensor-path state (warps 4-7) =================
    const int twid = wid - 4;            // 0..3 (valid when wid >= 4)
    const int warp_m = twid & 1;         // 0..1 -> 64-row slab
    const int warp_n = (twid >> 1) & 1;  // 0..1 -> 32-col slab in N[0,64)
    const uint32_t a_rel = (uint32_t)((warp_m * 64 + (lane & 15)) * ROW_STRIDE
                                      + (lane >> 4) * 16);
    const uint32_t b_rel = (uint32_t)(A_STAGE_BYTES
                         + (warp_n * 32 + (lane & 7) + ((lane >> 4) & 1) * 8) * ROW_STRIDE
                         + ((lane >> 3) & 1) * 16);
    int acc[4][4][4];

    // ================= dp4a-path state (warps 0-3) ===================
    const int dw = wid;                  // 0..3 -> 32-row M slab
    const int tr = lane >> 3;            // 0..3
    const int tc = lane & 7;             // 0..7
    const uint32_t da_rel = (uint32_t)((dw * 32 + tr) * ROW_STRIDE);
    const uint32_t db_rel = (uint32_t)(A_STAGE_BYTES + (64 + tc) * ROW_STRIDE);
    int dacc[8][8];

    if (wid >= 4) {
#pragma unroll
        for (int i = 0; i < 4; i++)
#pragma unroll
            for (int j = 0; j < 4; j++)
#pragma unroll
                for (int k = 0; k < 4; k++) acc[i][j][k] = 0;
    } else {
#pragma unroll
        for (int i = 0; i < 8; i++)
#pragma unroll
            for (int j = 0; j < 8; j++) dacc[i][j] = 0;
    }

    if (wid < 4) {
        // ---- loader coordinates (warps 0-3): 16 cpa16 per chunk ----
        const int l_lr = tid >> 3;                   // 0..15
        const int l_lc = (tid & 7) * 16;             // byte col in 128B row
        const int8_t* l_ag = g_xq + (size_t)(m_base + l_lr) * K_TOT + l_lc;
        const int8_t* l_bg = g_w  + (size_t)(n_base + l_lr) * K_TOT + l_lc;
        const uint32_t l_sw = (uint32_t)(l_lr * ROW_STRIDE + l_lc);

        // ---- prologue: fill stages 0 and 1 (chunks 0 and 1) ----
#pragma unroll
        for (int s = 0; s < 2; s++) {
            uint32_t st = STAGE_AT(s);
            int koff = s * TILE_KB;
#pragma unroll
            for (int i = 0; i < 8; i++) {
                cpa16(st + l_sw + i * 16 * ROW_STRIDE,
                      l_ag + koff + (size_t)i * 16 * K_TOT);
                cpa16(st + A_STAGE_BYTES + l_sw + i * 16 * ROW_STRIDE,
                      l_bg + koff + (size_t)i * 16 * K_TOT);
            }
            CPASYNC_MBAR_ARRIVE(BAR_FULL(s));
        }

        // ---- mainloop: loader + dp4a compute ----
        for (int kc = 0; kc < NCHUNK; kc++) {
            const int s = kc % NSTAGE;
            const int u = kc / NSTAGE;

            const int kl = kc + 2;                 // chunk to load ahead
            if (kl < NCHUNK) {
                const int sl = kl % NSTAGE;
                const int ul = kl / NSTAGE;
                if (ul >= 1)                       // stage reuse: wait consumed
                    MBARRIER_WAIT_PARITY(BAR_CONS(sl), (ul - 1) & 1);
                uint32_t st = STAGE_AT(sl);
                int koff = kl * TILE_KB;
#pragma unroll
                for (int i = 0; i < 8; i++) {
                    cpa16(st + l_sw + i * 16 * ROW_STRIDE,
                          l_ag + koff + (size_t)i * 16 * K_TOT);
                    cpa16(st + A_STAGE_BYTES + l_sw + i * 16 * ROW_STRIDE,
                          l_bg + koff + (size_t)i * 16 * K_TOT);
                }
                CPASYNC_MBAR_ARRIVE(BAR_FULL(sl));
            }

            MBARRIER_WAIT_PARITY(BAR_FULL(s), u & 1);
            const uint32_t st = STAGE_AT(s);

#pragma unroll 4
            for (int g = 0; g < 16; g++) {
                const uint32_t kb = (uint32_t)(g * 8);
                int2 av[8];
#pragma unroll
                for (int mt = 0; mt < 8; mt++) {
                    uint32_t ad = st + da_rel + (uint32_t)(mt * 4 * ROW_STRIDE) + kb;
                    asm volatile("ld.shared.v2.b32 {%0,%1}, [%2];"
                                 : "=r"(av[mt].x), "=r"(av[mt].y) : "r"(ad));
                }
#pragma unroll
                for (int half = 0; half < 2; half++) {
                    int2 bv[4];
#pragma unroll
                    for (int j = 0; j < 4; j++) {
                        uint32_t bd = st + db_rel
                            + (uint32_t)((half * 4 + j) * 8 * ROW_STRIDE) + kb;
                        asm volatile("ld.shared.v2.b32 {%0,%1}, [%2];"
                                     : "=r"(bv[j].x), "=r"(bv[j].y) : "r"(bd));
                    }
#pragma unroll
                    for (int j = 0; j < 4; j++) {
                        const int nt = half * 4 + j;
#pragma unroll
                        for (int mt = 0; mt < 8; mt++) {
                            int c = dp4a(av[mt].x, bv[j].x, dacc[mt][nt]);
                            dacc[mt][nt] = dp4a(av[mt].y, bv[j].y, c);
                        }
                    }
                }
            }
            MBARRIER_ARRIVE(BAR_CONS(s));
        }
    } else {
        // ---- mainloop: pure tensor compute (warps 4-7, HI priority) ----
        for (int kc = 0; kc < NCHUNK; kc++) {
            const int s = kc % NSTAGE;
            const int u = kc / NSTAGE;

            MBARRIER_WAIT_PARITY(BAR_FULL(s), u & 1);
            const uint32_t st = STAGE_AT(s);

            uint32_t b[2][2][4];                   // [buf][p][frag]
#pragma unroll
            for (int p = 0; p < 2; p++)
                ldsm4(b[0][p], st + b_rel + (uint32_t)(p * 16 * ROW_STRIDE));

#pragma unroll
            for (int kk = 0; kk < 4; kk++) {
                const int cur = kk & 1, nxt = cur ^ 1;
                if (kk < 3) {
#pragma unroll
                    for (int p = 0; p < 2; p++)
                        ldsm4(b[nxt][p],
                              st + b_rel + (uint32_t)(p * 16 * ROW_STRIDE + (kk + 1) * 32));
                }
                uint32_t afr[2][4];
                ldsm4(afr[0], st + a_rel + (uint32_t)(kk * 32));
#pragma unroll
                for (int mt = 0; mt < 4; mt++) {
                    if (mt < 3)
                        ldsm4(afr[(mt + 1) & 1],
                              st + a_rel + (uint32_t)((mt + 1) * 16 * ROW_STRIDE + kk * 32));
                    const int ab = mt & 1;
#pragma unroll
                    for (int nt = 0; nt < 4; nt++) {
                        imma16832(acc[mt][nt], afr[ab], b[cur][nt >> 1][(nt & 1) * 2],
                                  b[cur][nt >> 1][(nt & 1) * 2 + 1]);
                    }
                }
            }
            MBARRIER_ARRIVE(BAR_CONS(s));
        }
    }

    // ------------------------------ epilogue -------------------------------
    if (wid >= 4) {
        float rs0[4], rs1[4];
#pragma unroll
        for (int mt = 0; mt < 4; mt++) {
            int m = m_base + warp_m * 64 + mt * 16 + (lane >> 2);
            rs0[mt] = g_rowscale[m];
            rs1[mt] = g_rowscale[m + 8];
        }
#pragma unroll
        for (int nt = 0; nt < 4; nt++) {
            int n = n_base + warp_n * 32 + nt * 8 + 2 * (lane & 3);
            float2 bv2 = *reinterpret_cast<const float2*>(bias + n);
#pragma unroll
            for (int mt = 0; mt < 4; mt++) {
                int m = m_base + warp_m * 64 + mt * 16 + (lane >> 2);
                float2 v0, v1;
                v0.x = __int2float_rn(acc[mt][nt][0]) * rs0[mt] + bv2.x;
                v0.y = __int2float_rn(acc[mt][nt][1]) * rs0[mt] + bv2.y;
                v1.x = __int2float_rn(acc[mt][nt][2]) * rs1[mt] + bv2.x;
                v1.y = __int2float_rn(acc[mt][nt][3]) * rs1[mt] + bv2.y;
                *reinterpret_cast<float2*>(out + (size_t)m * N_TOT + n) = v0;
                *reinterpret_cast<float2*>(out + (size_t)(m + 8) * N_TOT + n) = v1;
            }
        }
    } else {
        float rs[8];
#pragma unroll
        for (int mt = 0; mt < 8; mt++)
            rs[mt] = g_rowscale[m_base + dw * 32 + mt * 4 + tr];
#pragma unroll
        for (int nt = 0; nt < 8; nt++) {
            int n = n_base + 64 + nt * 8 + tc;
            float bvv = bias[n];
#pragma unroll
            for (int mt = 0; mt < 8; mt++) {
                int m = m_base + dw * 32 + mt * 4 + tr;
                out[(size_t)m * N_TOT + n] =
                    __int2float_rn(dacc[mt][nt]) * rs[mt] + bvv;
            }
        }
    }
}

// ------------------------------- launcher ----------------------------------
extern "C" void kernel_launch(void* const* d_in, const int* in_sizes, int n_in,
                              void* d_out, int out_size) {
    const float* x    = (const float*)d_in[0];
    const int*   wp   = (const int*)d_in[1];
    const float* ws   = (const float*)d_in[2];
    const float* bias = (const float*)d_in[3];
    float*       out  = (float*)d_out;

    (void)in_sizes; (void)n_in; (void)out_size;

    static bool attr_set = false;
    if (!attr_set) {
        cudaFuncSetAttribute(gemm_kernel, cudaFuncAttributeMaxDynamicSharedMemorySize,
                             SMEM_BYTES);
        attr_set = true;
    }

    // 4 launches with gemm last keeps gemm at absolute launch #6 for ncu.
    prep_kernel<<<M_TOT + 4096, 256>>>(x, ws, wp);
    probe_kernel<<<1, 32>>>();
    probe_kernel<<<1, 32>>>();
    dim3 grid(N_TOT / TILE_N, M_TOT / TILE_M);
    gemm_kernel<<<grid, 256, SMEM_BYTES>>>(bias, out);
}